// round 17
// baseline (speedup 1.0000x reference)
#include <cuda_runtime.h>
#include <math.h>
#include <stdint.h>
#include <float.h>

#define MAXB  128
#define CAP   4096
#define NBINS 2048     // coarse subsample bins
#define FB    4096     // fine ranking bins
#define NTS   256      // sweep block threads (8 warps)
#define NT    1024     // finish block threads
#define WSEG  128      // per-warp candidate segment (32 segs * 128 = CAP per row)

// Global staging
__device__ float g_cval[MAXB * CAP];
__device__ int   g_cidx[MAXB * CAP];
__device__ int   g_wcnt[MAXB * 32];
__device__ float g_psum[MAXB * 4];
__device__ float g_thr [MAXB];

__device__ __forceinline__ int bin_of(float x) {
    int b = (int)floorf((x + 32.0f) * 32.0f);   // width 1/32 over [-32, 32]
    b = b < 0 ? 0 : b;
    return b > (NBINS - 1) ? (NBINS - 1) : b;
}

__device__ __forceinline__ float warp_red_sum(float v) {
    #pragma unroll
    for (int o = 16; o; o >>= 1) v += __shfl_xor_sync(0xffffffffu, v, o);
    return v;
}
__device__ __forceinline__ float warp_red_max(float v) {
    #pragma unroll
    for (int o = 16; o; o >>= 1) v = fmaxf(v, __shfl_xor_sync(0xffffffffu, v, o));
    return v;
}

// 1024-thread block scans (kFinish)
__device__ __forceinline__ float block_incl_scan(float v, float* wsum, int lane, int wid) {
    #pragma unroll
    for (int off = 1; off < 32; off <<= 1) {
        float n = __shfl_up_sync(0xffffffffu, v, off);
        if (lane >= off) v += n;
    }
    __syncthreads();
    if (lane == 31) wsum[wid] = v;
    __syncthreads();
    if (wid == 0) {
        float w = wsum[lane];
        #pragma unroll
        for (int off = 1; off < 32; off <<= 1) {
            float n = __shfl_up_sync(0xffffffffu, w, off);
            if (lane >= off) w += n;
        }
        wsum[lane] = w;
    }
    __syncthreads();
    return v + (wid ? wsum[wid - 1] : 0.f);
}
__device__ __forceinline__ int block_incl_scan_int(int v, int* wsum, int lane, int wid) {
    #pragma unroll
    for (int off = 1; off < 32; off <<= 1) {
        int n = __shfl_up_sync(0xffffffffu, v, off);
        if (lane >= off) v += n;
    }
    __syncthreads();
    if (lane == 31) wsum[wid] = v;
    __syncthreads();
    if (wid == 0) {
        int w = wsum[lane];
        #pragma unroll
        for (int off = 1; off < 32; off <<= 1) {
            int n = __shfl_up_sync(0xffffffffu, w, off);
            if (lane >= off) w += n;
        }
        wsum[lane] = w;
    }
    __syncthreads();
    return v + (wid ? wsum[wid - 1] : 0);
}

// order-preserving float <-> u32
__device__ __forceinline__ unsigned fmap(float x) {
    unsigned fb = __float_as_uint(x);
    return (fb & 0x80000000u) ? ~fb : (fb | 0x80000000u);
}
__device__ __forceinline__ float funmap(unsigned mu) {
    unsigned fb = (mu & 0x80000000u) ? (mu & 0x7FFFFFFFu) : ~mu;
    return __uint_as_float(fb);
}
__device__ __forceinline__ bool kv_gt(unsigned k1, unsigned p1, unsigned k2, unsigned p2) {
    return (k1 > k2) || (k1 == k2 && p1 < p2);   // key desc, idx asc
}
__device__ __forceinline__ void ce_sh(unsigned* kv, unsigned* pv, int i, int j, int K) {
    unsigned k1 = kv[i], p1 = pv[i], k2 = kv[i + j], p2 = pv[i + j];
    bool sw = ((i & K) == 0) ? kv_gt(k2, p2, k1, p1) : kv_gt(k1, p1, k2, p2);
    if (sw) { kv[i] = k2; pv[i] = p2; kv[i + j] = k1; pv[i + j] = p1; }
}

// =================== kSweep: 4 blocks/row x 256 threads ===================
__global__ void __launch_bounds__(NTS) kSweep(const float* __restrict__ logits,
                                              const float* __restrict__ temps,
                                              float* __restrict__ out,
                                              int V, int B, int tokens_first)
{
    const int row = blockIdx.x >> 2;
    const int sp  = blockIdx.x & 3;
    const int tid = threadIdx.x;
    const int lane = tid & 31, wid = tid >> 5;   // wid 0..7
    const unsigned lmlt = (1u << lane) - 1u;

    __shared__ int   hist[NBINS];
    __shared__ int   iws[8];
    __shared__ float wred[8];
    __shared__ int   s_bt;

    float* probs_out = tokens_first ? (out + B) : out;
    float* prow = probs_out + (size_t)row * V;
    const float* lrow = logits + (size_t)row * V;
    const float invT = 1.0f / temps[row];
    const int need = V < 1024 ? V : 1024;
    const int V4 = V >> 2;
    const float4* l4 = (const float4*)lrow;
    float4* p4 = (float4*)prow;
    const float4 z4 = make_float4(0.f, 0.f, 0.f, 0.f);

    if (tid == 0) s_bt = 1024;

    // ---- identical-per-block threshold: 16k contiguous-chunk subsample ----
    if (V > CAP) {
        for (int t = tid; t < NBINS; t += NTS) hist[t] = 0;
        __syncthreads();
        int Vq = V4 >> 2; if (Vq < 1) Vq = 1;
        for (int k = tid; k < 4096; k += NTS) {
            int c = k >> 10;
            int t = k & 1023;
            int pos = c * Vq + (t % Vq);
            if (pos >= V4) pos = V4 - 1;
            float4 v = l4[pos];
            if (v.x > 2.0f) atomicAdd(&hist[bin_of(v.x)], 1);
            if (v.y > 2.0f) atomicAdd(&hist[bin_of(v.y)], 1);
            if (v.z > 2.0f) atomicAdd(&hist[bin_of(v.z)], 1);
            if (v.w > 2.0f) atomicAdd(&hist[bin_of(v.w)], 1);
        }
        __syncthreads();
        const int subN = 16384;
        int tgt = (int)(((long long)need * 31LL * subN) / (20LL * (long long)V));
        if (tgt < 1) tgt = 1;
        // 960 bins (2047..1088), 4 consecutive-descending per thread (t<240)
        int cA = 0, cB = 0, cC = 0, cD = 0;
        if (tid < 240) {
            cA = hist[2047 - 4 * tid];
            cB = hist[2046 - 4 * tid];
            cC = hist[2045 - 4 * tid];
            cD = hist[2044 - 4 * tid];
        }
        int tot4 = cA + cB + cC + cD;
        // block-exclusive scan of tot4 over 256 threads
        int inc = tot4;
        #pragma unroll
        for (int off = 1; off < 32; off <<= 1) {
            int n = __shfl_up_sync(0xffffffffu, inc, off);
            if (lane >= off) inc += n;
        }
        if (lane == 31) iws[wid] = inc;
        __syncthreads();
        if (tid == 0) {
            int acc = 0;
            #pragma unroll
            for (int w = 0; w < 8; w++) { int t2 = iws[w]; iws[w] = acc; acc += t2; }
        }
        __syncthreads();
        int base = inc - tot4 + iws[wid];
        if (tid < 240) {
            int i0 = base + cA, i1 = i0 + cB, i2 = i1 + cC, i3 = i2 + cD;
            if (i0 >= tgt && base < tgt) s_bt = 2047 - 4 * tid;
            if (i1 >= tgt && i0   < tgt) s_bt = 2046 - 4 * tid;
            if (i2 >= tgt && i1   < tgt) s_bt = 2045 - 4 * tid;
            if (i3 >= tgt && i2   < tgt) s_bt = 2044 - 4 * tid;
        }
        __syncthreads();
    }
    const float xthr = (V > CAP) ? ((float)s_bt * 0.03125f - 32.0f) : -FLT_MAX;
    if (sp == 0 && tid == 0) g_thr[row] = xthr;

    // ---- quarter bounds (float4 units); scalar tail owned by sp==3 ----
    const int Vq4 = (V4 + 3) >> 2;
    const int qs = sp * Vq4;
    const int qe = (qs + Vq4 < V4) ? (qs + Vq4) : V4;

    const bool al = ((V & 3) == 0) && (((B & 3) == 0) || !tokens_first);
    if (!al) {
        for (int t = (qs << 2) + tid; t < (qe << 2); t += NTS) __stcs(prow + t, 0.f);
        if (sp == 3) for (int t = (V4 << 2) + tid; t < V; t += NTS) __stcs(prow + t, 0.f);
    }

    // ---- sweep quarter: fold zero-stores + loads + exp + segmented gather ----
    const int seg = sp * 8 + wid;                  // 0..31
    const int wbase = row * CAP + seg * WSEG;
    int wcnt = 0;

    #define GATHER4(vv, bi)                                                              \
        { bool p0 = (vv).x >= xthr, p1g = (vv).y >= xthr,                                \
               p2g = (vv).z >= xthr, p3g = (vv).w >= xthr;                               \
          unsigned m0 = __ballot_sync(0xffffffffu, p0);                                  \
          unsigned m1 = __ballot_sync(0xffffffffu, p1g);                                 \
          unsigned m2 = __ballot_sync(0xffffffffu, p2g);                                 \
          unsigned m3 = __ballot_sync(0xffffffffu, p3g);                                 \
          int c0 = __popc(m0), c1 = __popc(m1), c2 = __popc(m2), c3 = __popc(m3);        \
          int o0 = wcnt + __popc(m0 & lmlt);                                             \
          int o1 = wcnt + c0 + __popc(m1 & lmlt);                                        \
          int o2 = wcnt + c0 + c1 + __popc(m2 & lmlt);                                   \
          int o3 = wcnt + c0 + c1 + c2 + __popc(m3 & lmlt);                              \
          if (p0 && o0 < WSEG) { g_cval[wbase + o0] = (vv).x; g_cidx[wbase + o0] = ((bi) << 2) + 0; } \
          if (p1g && o1 < WSEG) { g_cval[wbase + o1] = (vv).y; g_cidx[wbase + o1] = ((bi) << 2) + 1; } \
          if (p2g && o2 < WSEG) { g_cval[wbase + o2] = (vv).z; g_cidx[wbase + o2] = ((bi) << 2) + 2; } \
          if (p3g && o3 < WSEG) { g_cval[wbase + o3] = (vv).w; g_cidx[wbase + o3] = ((bi) << 2) + 3; } \
          wcnt += (c0 + c1) + (c2 + c3); }

    float sA = 0.f, sB = 0.f, sC = 0.f, sD = 0.f;
    int i = qs + tid;
    // main 4-way loop, warp-uniform guard (lanes consecutive: i - lane is warp base)
    while (i - lane + 3 * NTS + 32 <= qe) {
        if (al) {
            __stcs(p4 + i, z4);
            __stcs(p4 + i + NTS, z4);
            __stcs(p4 + i + 2 * NTS, z4);
            __stcs(p4 + i + 3 * NTS, z4);
        }
        float4 va = l4[i];
        float4 vb = l4[i + NTS];
        float4 vc = l4[i + 2 * NTS];
        float4 vd = l4[i + 3 * NTS];
        sA += __expf(va.x * invT) + __expf(va.y * invT) + __expf(va.z * invT) + __expf(va.w * invT);
        sB += __expf(vb.x * invT) + __expf(vb.y * invT) + __expf(vb.z * invT) + __expf(vb.w * invT);
        sC += __expf(vc.x * invT) + __expf(vc.y * invT) + __expf(vc.z * invT) + __expf(vc.w * invT);
        sD += __expf(vd.x * invT) + __expf(vd.y * invT) + __expf(vd.z * invT) + __expf(vd.w * invT);
        GATHER4(va, i);
        GATHER4(vb, i + NTS);
        GATHER4(vc, i + 2 * NTS);
        GATHER4(vd, i + 3 * NTS);
        i += 4 * NTS;
    }
    // remainder: whole-warp predicated
    for (; i - lane < qe; i += NTS) {
        bool in = i < qe;
        float4 v = in ? l4[i] : make_float4(-FLT_MAX, -FLT_MAX, -FLT_MAX, -FLT_MAX);
        if (in) {
            if (al) __stcs(p4 + i, z4);
            sA += __expf(v.x * invT) + __expf(v.y * invT) + __expf(v.z * invT) + __expf(v.w * invT);
        }
        GATHER4(v, i);   // -FLT_MAX padding never passes xthr
    }
    #undef GATHER4
    float s = (sA + sB) + (sC + sD);
    if (sp == 3) {   // scalar tail (V % 4), predicated whole-warp
        for (int t = (V4 << 2) + tid; t - lane < V; t += NTS) {
            bool in = t < V;
            float x = in ? lrow[t] : -FLT_MAX;
            if (in) {
                if (al) __stcs(prow + t, 0.f);
                s += __expf(x * invT);
            }
            bool pred = in && (x >= xthr);
            unsigned m = __ballot_sync(0xffffffffu, pred);
            int pos = wcnt + __popc(m & lmlt);
            if (pred && pos < WSEG) { g_cval[wbase + pos] = x; g_cidx[wbase + pos] = t; }
            wcnt += __popc(m);
        }
    }
    if (lane == 0) g_wcnt[row * 32 + seg] = wcnt;

    // partial sum reduce over 8 warps
    s = warp_red_sum(s);
    if (lane == 0) wred[wid] = s;
    __syncthreads();
    if (tid == 0) {
        float t = 0.f;
        #pragma unroll
        for (int w = 0; w < 8; w++) t += wred[w];
        g_psum[row * 4 + sp] = t;
    }
}

// =================== kFinish: 1 block/row x 1024 threads ===================
__global__ void __launch_bounds__(NT) kFinish(const float* __restrict__ logits,
                                              const float* __restrict__ temps,
                                              const int*   __restrict__ top_ks,
                                              const float* __restrict__ top_ps,
                                              const float* __restrict__ min_ps,
                                              const float* __restrict__ u,
                                              float* __restrict__ out,
                                              int V, int B, int tokens_first)
{
    const int row = blockIdx.x;
    const int tid = threadIdx.x;
    const int lane = tid & 31, wid = tid >> 5;

    __shared__ unsigned arena[8192];       // 32 KB phase-aliased
    __shared__ float wred[32];
    __shared__ int   iwsum[32];
    __shared__ int   scnt[32];
    __shared__ float s_S, s_shift, s_mx, s_lo;
    __shared__ int   s_bt, s_cnt, s_bad;
    __shared__ float sh_p0, sh_tot;

    int* hist = (int*)arena;

    float* probs_out = tokens_first ? (out + B) : out;
    float* prow = probs_out + (size_t)row * V;
    const float* lrow = logits + (size_t)row * V;
    const float invT = 1.0f / temps[row];
    const int need = V < 1024 ? V : 1024;

    if (tid < 32) scnt[tid] = g_wcnt[row * 32 + tid];
    if (tid == 0) {
        s_bad = 0;
        s_lo = g_thr[row];
        float S = 0.f;
        #pragma unroll
        for (int sp = 0; sp < 4; sp++) S += g_psum[row * 4 + sp];
        s_S = S;
    }
    __syncthreads();

    // total count + overflow
    int ovf = 0;
    if (wid == 0) {
        int c = scnt[lane];
        int o = (c > WSEG) ? 1 : 0;
        #pragma unroll
        for (int off = 16; off; off >>= 1) {
            c += __shfl_xor_sync(0xffffffffu, c, off);
            o += __shfl_xor_sync(0xffffffffu, o, off);
        }
        if (lane == 0) { s_cnt = c; iwsum[31] = o; }
    }
    __syncthreads();
    int C = s_cnt;
    ovf = iwsum[31];
    __syncthreads();

    bool segmented = (V > CAP);
    const bool bad = segmented && (ovf || !(C >= need && C <= 2048));

    // candidate slots (loaded once; reused by phase 4 fast path)
    float xv[4]; int xi[4]; bool val[4];
    #pragma unroll
    for (int e = 0; e < 4; e++) val[e] = false;

    float mx = -FLT_MAX;
    if (segmented && !bad) {
        #pragma unroll
        for (int e = 0; e < 4; e++) {
            int slot = tid + e * NT;
            int w = slot >> 7, j = slot & (WSEG - 1);
            val[e] = j < scnt[w];
            if (val[e]) {
                xv[e] = g_cval[row * CAP + slot];
                xi[e] = g_cidx[row * CAP + slot];
                mx = fmaxf(mx, xv[e]);
            }
        }
    } else if (V <= CAP) {
        segmented = false;
        for (int t = tid; t < V; t += NT) { g_cval[row * CAP + t] = lrow[t]; g_cidx[row * CAP + t] = t; }
        if (tid == 0) s_cnt = V;
        __syncthreads();
        C = V;
        for (int t = tid; t < V; t += NT) mx = fmaxf(mx, lrow[t]);
    } else {
        // FALLBACK (~never): exact coarse histogram + exact max in one pass
        segmented = false;
        for (int t = tid; t < NBINS; t += NT) hist[t] = 0;
        __syncthreads();
        for (int t = tid; t < V; t += NT) {
            float x = lrow[t];
            mx = fmaxf(mx, x);
            atomicAdd(&hist[bin_of(x)], 1);
        }
        __syncthreads();
        if (tid == 0) {
            int acc = 0, bt2 = 0;
            for (int b = NBINS - 1; b >= 0; b--) {
                int na = acc + hist[b];
                if (na >= need) { bt2 = (na <= CAP) ? b : (b + 1); break; }
                acc = na;
            }
            s_bt = bt2; s_cnt = 0;
            s_lo = (float)bt2 * 0.03125f - 32.0f - 0.0625f;
        }
        __syncthreads();
        const int bt2 = s_bt;
        for (int t = tid; t < V; t += NT) {
            float x = lrow[t];
            if (bin_of(x) >= bt2) {
                int pos = atomicAdd(&s_cnt, 1);
                if (pos < CAP) { g_cval[row * CAP + pos] = x; g_cidx[row * CAP + pos] = t; }
            }
        }
        __syncthreads();
        C = s_cnt;
    }
    C = C < CAP ? C : CAP;

    // block-reduce max
    mx = warp_red_max(mx);
    __syncthreads();
    if (lane == 0) wred[wid] = mx;
    __syncthreads();
    if (wid == 0) {
        float t = warp_red_max(wred[lane]);
        if (lane == 0) {
            s_mx = t;
            float mxT = t * invT;
            s_shift = (mxT > 80.f || !isfinite(s_S)) ? mxT : 0.f;
        }
    }
    __syncthreads();
    const float shift = s_shift;
    if (shift != 0.f) {        // rare overflow-safe recompute (precise path)
        float s2 = 0.f;
        for (int t = tid; t < V; t += NT) s2 += expf(lrow[t] * invT - shift);
        s2 = warp_red_sum(s2);
        if (lane == 0) wred[wid] = s2;
        __syncthreads();
        if (wid == 0) { float t = warp_red_sum(wred[lane]); if (lane == 0) s_S = t; }
        __syncthreads();
    }

    // ---- Phase 4: histogram ranking ----
    const float lo = s_lo, hi = s_mx;
    const float range = hi - lo;
    int*      bins = (int*)arena;
    unsigned* skv  = arena + 4096;
    unsigned* skp  = arena + 6144;
    unsigned *pk = skv, *pp = skp;

    bool fast = segmented && (C <= 2048) && (range > 0.f) && isfinite(range);

    if (fast) {
        const float scale = (float)FB / range;
        int xb[4];
        #pragma unroll
        for (int t = 0; t < 4; t++) bins[tid + t * NT] = 0;
        __syncthreads();
        #pragma unroll
        for (int e = 0; e < 4; e++) {
            if (val[e]) {
                int b = (int)((xv[e] - lo) * scale); b = b < 0 ? 0 : (b > FB - 1 ? FB - 1 : b);
                xb[e] = b;
                atomicAdd(&bins[b], 1);
            }
        }
        __syncthreads();
        int c0c = bins[4095 - 4 * tid];
        int c1c = bins[4094 - 4 * tid];
        int c2c = bins[4093 - 4 * tid];
        int c3c = bins[4092 - 4 * tid];
        int tot4 = c0c + c1c + c2c + c3c;
        int base = block_incl_scan_int(tot4, iwsum, lane, wid) - tot4;
        bins[4095 - 4 * tid] = base;
        bins[4094 - 4 * tid] = base + c0c;
        bins[4093 - 4 * tid] = base + c0c + c1c;
        bins[4092 - 4 * tid] = base + c0c + c1c + c2c;
        __syncthreads();
        #pragma unroll
        for (int e = 0; e < 4; e++) {
            if (val[e]) {
                int sl = atomicAdd(&bins[xb[e]], 1);
                skv[sl] = fmap(xv[e]); skp[sl] = (unsigned)xi[e];
            }
        }
        __syncthreads();
        // fixup within-bin order: insertion sort on contiguous same-bin runs
        #pragma unroll
        for (int e = 0; e < 2; e++) {
            int ii = tid + e * 1024;
            if (ii < C) {
                int bi = (int)((funmap(skv[ii]) - lo) * scale); bi = bi < 0 ? 0 : (bi > FB - 1 ? FB - 1 : bi);
                int bp = -1;
                if (ii > 0) {
                    bp = (int)((funmap(skv[ii - 1]) - lo) * scale); bp = bp < 0 ? 0 : (bp > FB - 1 ? FB - 1 : bp);
                }
                if (bi != bp) {                       // run start
                    int L = 1;
                    while (ii + L < C && L <= 16) {
                        int bn = (int)((funmap(skv[ii + L]) - lo) * scale); bn = bn < 0 ? 0 : (bn > FB - 1 ? FB - 1 : bn);
                        if (bn != bi) break;
                        L++;
                    }
                    if (L > 16) { atomicExch(&s_bad, 1); }
                    else if (L > 1) {
                        unsigned lk[16], lp[16];
                        for (int t = 0; t < L; t++) { lk[t] = skv[ii + t]; lp[t] = skp[ii + t]; }
                        for (int a = 1; a < L; a++) {
                            unsigned ck = lk[a], cp = lp[a];
                            int b2 = a - 1;
                            while (b2 >= 0 && !kv_gt(lk[b2], lp[b2], ck, cp)) {
                                lk[b2 + 1] = lk[b2]; lp[b2 + 1] = lp[b2]; b2--;
                            }
                            lk[b2 + 1] = ck; lp[b2 + 1] = cp;
                        }
                        for (int t = 0; t < L; t++) { skv[ii + t] = lk[t]; skp[ii + t] = lp[t]; }
                    }
                }
            }
        }
        __syncthreads();
        if (s_bad) fast = false;
        __syncthreads();
    }

    if (!fast) {
        // exact bitonic on 4096 (rare). Compact segmented candidates first.
        if (segmented) {
            unsigned* ckv = arena;
            unsigned* ckp = arena + 4096;
            if (wid == 0) {
                int c = scnt[lane] <= WSEG ? scnt[lane] : WSEG;
                int inc = c;
                #pragma unroll
                for (int off = 1; off < 32; off <<= 1) {
                    int n = __shfl_up_sync(0xffffffffu, inc, off);
                    if (lane >= off) inc += n;
                }
                iwsum[lane] = inc - c;
            }
            __syncthreads();
            #pragma unroll
            for (int e = 0; e < 4; e++) {
                int slot = tid + e * NT;
                int w = slot >> 7, j = slot & (WSEG - 1);
                if (j < scnt[w]) {
                    int dst = iwsum[w] + j;
                    ckv[dst] = fmap(g_cval[row * CAP + slot]);
                    ckp[dst] = (unsigned)g_cidx[row * CAP + slot];
                }
            }
            __syncthreads();
            for (int ii = tid; ii < CAP; ii += NT) {
                if (ii >= C) { ckv[ii] = 0u; ckp[ii] = 0xFFFFFFFFu; }
            }
            __syncthreads();
        } else {
            unsigned* ckv = arena;
            unsigned* ckp = arena + 4096;
            for (int ii = tid; ii < CAP; ii += NT) {
                unsigned key = 0u, pay = 0xFFFFFFFFu;
                if (ii < C) { key = fmap(g_cval[row * CAP + ii]); pay = (unsigned)g_cidx[row * CAP + ii]; }
                ckv[ii] = key; ckp[ii] = pay;
            }
            __syncthreads();
        }
        unsigned* fkv = arena;
        unsigned* fkp = arena + 4096;
        for (int K = 2; K <= CAP; K <<= 1) {
            int j = K >> 1;
            for (; j >= 64; j >>= 1) {
                for (int c = tid; c < (CAP >> 1); c += NT) {
                    int ii = ((c & ~(j - 1)) << 1) | (c & (j - 1));
                    ce_sh(fkv, fkp, ii, j, K);
                }
                __syncthreads();
            }
            for (; j >= 1; j >>= 1) {
                for (int c = tid; c < (CAP >> 1); c += NT) {
                    int ii = ((c & ~(j - 1)) << 1) | (c & (j - 1));
                    ce_sh(fkv, fkp, ii, j, K);
                }
                __syncwarp();
            }
            __syncthreads();
        }
        pk = fkv; pp = fkp;
    }

    // ---- Phase 5: masks (reference order) + inverse-CDF sample + scatter ----
    const float S = s_S;
    float p = 0.f;
    int   myidx = 0;
    if (tid < C) {
        p = expf(funmap(pk[tid]) * invT - shift) / S;
        myidx = (int)pp[tid];
    }
    if (tid == 0) sh_p0 = p;

    float cumincl = block_incl_scan(p, wred, lane, wid);   // pre-mask cumsum

    const int   tk  = top_ks[row];
    const float tp  = top_ps[row];
    const float thr = sh_p0 * min_ps[row];
    float q = p;
    if (tid >= tk)        q = 0.f;   // top-k
    if (cumincl - q > tp) q = 0.f;   // top-p (cumsum computed pre-mask)
    if (q < thr)          q = 0.f;   // min-p

    float cq = block_incl_scan(q, wred, lane, wid);        // post-mask CDF numerator
    if (tid == NT - 1) sh_tot = cq;
    __syncthreads();
    const float tot  = sh_tot;
    const float uval = u[row];

    int rank = __syncthreads_count((cq / tot < uval) ? 1 : 0);
    if (rank > NT - 1) rank = NT - 1;
    if (rank > V - 1) rank = V - 1;

    if (tid == 0 && tokens_first) {
        out[row] = (float)(int)pp[rank];
    }
    if (q > 0.f) {
        prow[myidx] = q / tot;       // row zeroed by kSweep (prior kernel)
    }
}

extern "C" void kernel_launch(void* const* d_in, const int* in_sizes, int n_in,
                              void* d_out, int out_size)
{
    const float* logits = (const float*)d_in[0];
    const float* temps  = (const float*)d_in[1];
    const int*   topks  = (const int*)  d_in[2];
    const float* topps  = (const float*)d_in[3];
    const float* minps  = (const float*)d_in[4];
    const float* u      = (const float*)d_in[5];

    const int B = in_sizes[1];
    const int V = in_sizes[0] / B;
    float* out = (float*)d_out;
    int tokens_first = (out_size == B + B * V) ? 1 : 0;

    kSweep <<<B * 4, NTS>>>(logits, temps, out, V, B, tokens_first);
    kFinish<<<B, NT>>>(logits, temps, topks, topps, minps, u, out, V, B, tokens_first);
}